// round 7
// baseline (speedup 1.0000x reference)
#include <cuda_runtime.h>

// ---------------- problem constants ----------------
#define N_NODES  50000
#define N_EDGES  640000
#define N_GRAPHS 64
#define IN_DIM   128
#define HID      256
#define HID2     128   // HID/2
#define OUT_DIM  4

// ---------------- scratch (static device arrays; no allocation) ----------------
// RULE (root cause of rounds 1-6): these symbols are ONLY referenced inside
// device code. They are NEVER passed as kernel arguments from host code
// (host-side symbol decay yields the host shadow address, which GB300's ATS
// happily dereferences -> silent wrong buffer).
__device__ float  g_dinv[N_NODES];                 // deg -> rsqrt(deg)
__device__ float4 g_agg1[N_NODES * (IN_DIM / 4)];  // aggregated x      [N,128]
__device__ float  g_h1 [N_NODES * HID];            // relu(agg1@W1+b1)  [N,256]
__device__ float4 g_m2  [N_NODES * (HID2 / 4)];    // h1@W2             [N,128]
__device__ float4 g_agg2[N_NODES * (HID2 / 4)];    // aggregated m2     [N,128]
__device__ float  g_pool[N_GRAPHS * HID2];         // per-graph sums
__device__ float  g_cnt [N_GRAPHS];                // per-graph counts
__device__ int    g_idx64;                         // 1 if index arrays are int64

// ---------------- helpers ----------------
__device__ __forceinline__ void red_add_v4(float* addr, float4 v) {
    asm volatile("red.global.add.v4.f32 [%0], {%1,%2,%3,%4};"
                 :: "l"(addr), "f"(v.x), "f"(v.y), "f"(v.z), "f"(v.w)
                 : "memory");
}

__device__ __forceinline__ int get_idx(const void* p, int i, int is64) {
    long long v;
    if (is64) v = __ldg(((const long long*)p) + i);
    else      v = __ldg(((const int*)p) + i);
    return (int)v;
}

// ---------------- index dtype detection ----------------
__global__ void k_detect(const int* p) {
    int lane = threadIdx.x;
    int nz = 0;
    for (int i = lane; i < 4096; i += 32)
        if (p[2 * i + 1] != 0) nz = 1;
    unsigned m = __ballot_sync(0xffffffffu, nz);
    if (lane == 0) g_idx64 = (m == 0u) ? 1 : 0;
}

// ---------------- degree / norm ----------------
__global__ void k_deg_init() {
    int i = blockIdx.x * blockDim.x + threadIdx.x;
    if (i < N_NODES) g_dinv[i] = 1.0f;     // +1 self loop
}

__global__ void k_deg_count(const void* __restrict__ dst) {
    int e = blockIdx.x * blockDim.x + threadIdx.x;
    if (e < N_EDGES) {
        int d = get_idx(dst, e, g_idx64);
        if ((unsigned)d < (unsigned)N_NODES) atomicAdd(&g_dinv[d], 1.0f);
    }
}

__global__ void k_rsqrt() {
    int i = blockIdx.x * blockDim.x + threadIdx.x;
    if (i < N_NODES) g_dinv[i] = rsqrtf(g_dinv[i]);
}

// ---------------- aggregation init: agg = feat * dinv^2 (self-loop term) ----------------
__global__ void k_init_agg1(const float4* __restrict__ x) {
    int t = blockIdx.x * blockDim.x + threadIdx.x;     // node*32 + j
    if (t >= N_NODES * 32) return;
    int node = t >> 5;
    float di = g_dinv[node];
    float s = di * di;
    float4 v = x[t];
    v.x *= s; v.y *= s; v.z *= s; v.w *= s;
    g_agg1[t] = v;
}

__global__ void k_init_agg2() {
    int t = blockIdx.x * blockDim.x + threadIdx.x;
    if (t >= N_NODES * 32) return;
    int node = t >> 5;
    float di = g_dinv[node];
    float s = di * di;
    float4 v = g_m2[t];
    v.x *= s; v.y *= s; v.z *= s; v.w *= s;
    g_agg2[t] = v;
}

// ---------------- edge scatter: agg[dst] += feat[src]*dinv[s]*dinv[d] ----------------
// One warp per edge, one float4 per lane. Layer variants bind scratch symbols
// in DEVICE code; only true device pointers (x, src, dst) cross the boundary.
__global__ void k_edge1(const float4* __restrict__ x,
                        const void* __restrict__ src, const void* __restrict__ dst) {
    int t = blockIdx.x * blockDim.x + threadIdx.x;
    int e = t >> 5;
    if (e >= N_EDGES) return;
    int is64 = g_idx64;
    int j = t & 31;
    int s = get_idx(src, e, is64);
    int d = get_idx(dst, e, is64);
    if ((unsigned)s >= (unsigned)N_NODES || (unsigned)d >= (unsigned)N_NODES) return;
    float norm = g_dinv[s] * g_dinv[d];
    float4 v = x[(size_t)s * 32 + j];
    v.x *= norm; v.y *= norm; v.z *= norm; v.w *= norm;
    red_add_v4((float*)(g_agg1 + (size_t)d * 32 + j), v);
}

__global__ void k_edge2(const void* __restrict__ src, const void* __restrict__ dst) {
    int t = blockIdx.x * blockDim.x + threadIdx.x;
    int e = t >> 5;
    if (e >= N_EDGES) return;
    int is64 = g_idx64;
    int j = t & 31;
    int s = get_idx(src, e, is64);
    int d = get_idx(dst, e, is64);
    if ((unsigned)s >= (unsigned)N_NODES || (unsigned)d >= (unsigned)N_NODES) return;
    float norm = g_dinv[s] * g_dinv[d];
    float4 v = g_m2[(size_t)s * 32 + j];
    v.x *= norm; v.y *= norm; v.z *= norm; v.w *= norm;
    red_add_v4((float*)(g_agg2 + (size_t)d * 32 + j), v);
}

// ---------------- SGEMM: C[M,N] = A[M,K] @ B[K,N] (+bias, relu) ----------------
// BM=BN=128, BK=8, 256 threads, 8x8 microtile per thread.
template <int KDIM, int NDIM, bool RELU_BIAS>
__device__ __forceinline__ void sgemm_body(const float* __restrict__ A,
                                           const float* __restrict__ B,
                                           const float* __restrict__ bias,
                                           float* __restrict__ C) {
    constexpr int BM = 128, BN = 128, BK = 8;
    __shared__ float As[BK][BM];   // A tile transposed
    __shared__ float Bs[BK][BN];

    const int t    = threadIdx.x;            // 0..255
    const int cRow = blockIdx.y * BM;
    const int cCol = blockIdx.x * BN;
    const int tx   = t & 15;                  // col group
    const int ty   = t >> 4;                  // row group

    const int arow = cRow + (t >> 1);
    const int acol = (t & 1) * 4;
    const int brow = t >> 5;
    const int bcol = (t & 31) * 4;

    float acc[8][8];
    #pragma unroll
    for (int i = 0; i < 8; i++)
        #pragma unroll
        for (int j = 0; j < 8; j++) acc[i][j] = 0.0f;

    for (int k0 = 0; k0 < KDIM; k0 += BK) {
        float4 av = make_float4(0.f, 0.f, 0.f, 0.f);
        if (arow < N_NODES)
            av = *(const float4*)(A + (size_t)arow * KDIM + k0 + acol);
        As[acol + 0][t >> 1] = av.x;
        As[acol + 1][t >> 1] = av.y;
        As[acol + 2][t >> 1] = av.z;
        As[acol + 3][t >> 1] = av.w;

        *(float4*)&Bs[brow][bcol] =
            *(const float4*)(B + (size_t)(k0 + brow) * NDIM + cCol + bcol);
        __syncthreads();

        #pragma unroll
        for (int k = 0; k < BK; k++) {
            float ra[8], rb[8];
            #pragma unroll
            for (int i = 0; i < 8; i++) ra[i] = As[k][ty * 8 + i];
            #pragma unroll
            for (int j = 0; j < 8; j++) rb[j] = Bs[k][tx * 8 + j];
            #pragma unroll
            for (int i = 0; i < 8; i++)
                #pragma unroll
                for (int j = 0; j < 8; j++)
                    acc[i][j] = fmaf(ra[i], rb[j], acc[i][j]);
        }
        __syncthreads();
    }

    #pragma unroll
    for (int i = 0; i < 8; i++) {
        int r = cRow + ty * 8 + i;
        if (r < N_NODES) {
            #pragma unroll
            for (int jj = 0; jj < 8; jj += 4) {
                int c = cCol + tx * 8 + jj;
                float4 v = make_float4(acc[i][jj], acc[i][jj + 1],
                                       acc[i][jj + 2], acc[i][jj + 3]);
                if (RELU_BIAS) {
                    const float4 bb = *(const float4*)(bias + c);
                    v.x = fmaxf(v.x + bb.x, 0.f);
                    v.y = fmaxf(v.y + bb.y, 0.f);
                    v.z = fmaxf(v.z + bb.z, 0.f);
                    v.w = fmaxf(v.w + bb.w, 0.f);
                }
                *(float4*)(C + (size_t)r * NDIM + c) = v;
            }
        }
    }
}

__global__ void __launch_bounds__(256) k_gemm1(const float* __restrict__ W1,
                                               const float* __restrict__ b1) {
    sgemm_body<IN_DIM, HID, true>((const float*)g_agg1, W1, b1, g_h1);
}

__global__ void __launch_bounds__(256) k_gemm2(const float* __restrict__ W2) {
    sgemm_body<HID, HID2, false>(g_h1, W2, nullptr, (float*)g_m2);
}

// ---------------- pooling ----------------
__global__ void k_zero_pool() {
    int i = blockIdx.x * blockDim.x + threadIdx.x;
    if (i < N_GRAPHS * HID2) g_pool[i] = 0.0f;
    if (i < N_GRAPHS) g_cnt[i] = 0.0f;
}

// h2 = relu(agg2 + b2), scatter-add into per-graph sums + counts
__global__ void k_pool(const void* __restrict__ batch, const float* __restrict__ b2) {
    int t = blockIdx.x * blockDim.x + threadIdx.x;
    if (t >= N_NODES * 32) return;
    int node = t >> 5;
    int j    = t & 31;
    int b    = get_idx(batch, node, g_idx64);
    if ((unsigned)b >= (unsigned)N_GRAPHS) return;
    float4 v  = g_agg2[t];
    float4 bb = ((const float4*)b2)[j];
    v.x = fmaxf(v.x + bb.x, 0.f);
    v.y = fmaxf(v.y + bb.y, 0.f);
    v.z = fmaxf(v.z + bb.z, 0.f);
    v.w = fmaxf(v.w + bb.w, 0.f);
    red_add_v4(&g_pool[b * HID2 + j * 4], v);
    if (j == 0) atomicAdd(&g_cnt[b], 1.0f);
}

// out[g,o] = (pool[g]/cnt[g]) @ Wfc + bfc
__global__ void k_out(const float* __restrict__ Wfc, const float* __restrict__ bfc,
                      float* __restrict__ out) {
    int t = threadIdx.x;
    if (t >= N_GRAPHS * OUT_DIM) return;
    int g = t >> 2;
    int o = t & 3;
    float inv = 1.0f / fmaxf(g_cnt[g], 1.0f);
    float s = 0.0f;
    #pragma unroll 16
    for (int k = 0; k < HID2; k++)
        s = fmaf(g_pool[g * HID2 + k], Wfc[k * OUT_DIM + o], s);
    out[t] = s * inv + bfc[o];
}

// ---------------- launch ----------------
extern "C" void kernel_launch(void* const* d_in, const int* in_sizes, int n_in,
                              void* d_out, int out_size) {
    // identify inputs by element count (robust to metadata ordering)
    int ix = -1, isrc = -1, idst = -1, ibatch = -1, iW1 = -1, iW2 = -1;
    int ib1 = -1, ib2 = -1, iWfc = -1, ibfc = -1;
    for (int i = 0; i < n_in; i++) {
        int s = in_sizes[i];
        if      (s == N_NODES * IN_DIM)  ix = i;
        else if (s == N_EDGES)           { if (isrc < 0) isrc = i; else idst = i; }
        else if (s == N_NODES)           ibatch = i;
        else if (s == IN_DIM * HID)      { if (iW1 < 0) iW1 = i; else iW2 = i; }
        else if (s == HID)               ib1 = i;
        else if (s == HID2)              ib2 = i;
        else if (s == HID2 * OUT_DIM)    iWfc = i;
        else if (s == OUT_DIM)           ibfc = i;
    }
    if (in_sizes[0] != N_NODES * IN_DIM) { int tmp = isrc; isrc = idst; idst = tmp; }

    const float* x     = (const float*)d_in[ix];
    const void*  src   = d_in[isrc];
    const void*  dst   = d_in[idst];
    const void*  batch = d_in[ibatch];
    const float* W1    = (const float*)d_in[iW1];
    const float* b1    = (const float*)d_in[ib1];
    const float* W2    = (const float*)d_in[iW2];
    const float* b2    = (const float*)d_in[ib2];
    const float* Wfc   = (const float*)d_in[iWfc];
    const float* bfc   = (const float*)d_in[ibfc];
    float* out = (float*)d_out;

    const int TPB = 256;
    const int nodeBlocks  = (N_NODES + TPB - 1) / TPB;
    const int edgeBlocks  = (N_EDGES + TPB - 1) / TPB;
    const int nvecBlocks  = (N_NODES * 32 + TPB - 1) / TPB;   // node*32 threads
    const int evecBlocks  = (N_EDGES * 32 + TPB - 1) / TPB;   // edge*32 threads

    k_detect<<<1, 32>>>((const int*)src);

    // degree + normalization
    k_deg_init <<<nodeBlocks, TPB>>>();
    k_deg_count<<<edgeBlocks, TPB>>>(dst);
    k_rsqrt    <<<nodeBlocks, TPB>>>();

    // layer 1: aggregate x first (128-dim), then GEMM (+bias,relu)
    k_init_agg1<<<nvecBlocks, TPB>>>((const float4*)x);
    k_edge1    <<<evecBlocks, TPB>>>((const float4*)x, src, dst);
    {
        dim3 grid(HID / 128, (N_NODES + 127) / 128);
        k_gemm1<<<grid, 256>>>(W1, b1);
    }

    // layer 2: GEMM first (output 128-dim), then aggregate
    {
        dim3 grid(HID2 / 128, (N_NODES + 127) / 128);
        k_gemm2<<<grid, 256>>>(W2);
    }
    k_init_agg2<<<nvecBlocks, TPB>>>();
    k_edge2    <<<evecBlocks, TPB>>>(src, dst);

    // pool + fc
    k_zero_pool<<<(N_GRAPHS * HID2 + TPB - 1) / TPB, TPB>>>();
    k_pool     <<<nvecBlocks, TPB>>>(batch, b2);
    k_out      <<<1, N_GRAPHS * OUT_DIM>>>(Wfc, bfc, out);
}